// round 7
// baseline (speedup 1.0000x reference)
#include <cuda_runtime.h>
#include <cuda_bf16.h>
#include <cstdint>

// Problem constants:
//   N=50000 nodes, E=800000 edges, IN_DIM=128, H=8, D=16 -> C = H*D = 128
#define NN 50000
#define EE 800000
#define CC 128
#define KK 128

typedef unsigned long long ull;

// ---------------- device scratch (zero-initialized at module load) ----------
__device__ float d_z[NN * CC];          // per-node projected features [N,128]
__device__ int   d_cnt[NN];             // degree histogram -> scatter cursor (tail-zeroed)
__device__ int   d_off[NN + 1];         // CSR row offsets by dst
__device__ int   d_csr_src[EE];         // src ids grouped by dst

#define SB   512
#define NBLK ((NN + SB - 1) / SB)       // 98 (<= 148 SMs: all resident, lookback safe)
__device__ int d_incl[NBLK];            // inclusive prefix + 1 (0 = not ready); tail-zeroed

// ---------------- CSR construction ------------------------------------------
// 4 edges per thread via one int4 load (E divisible by 4).
__global__ void k_hist(const int4* __restrict__ dst4) {
    int t = blockIdx.x * blockDim.x + threadIdx.x;
    if (t < EE / 4) {
        int4 d = __ldg(&dst4[t]);
        atomicAdd(&d_cnt[d.x], 1);
        atomicAdd(&d_cnt[d.y], 1);
        atomicAdd(&d_cnt[d.z], 1);
        atomicAdd(&d_cnt[d.w], 1);
    }
}

// Single-launch deterministic lookback scan. Requires d_incl == 0 on entry
// (module-load zeroing on first call; tail-zero kernel thereafter).
__global__ void __launch_bounds__(SB) k_scan() {
    __shared__ int s[SB];
    __shared__ int s_prev;
    const int b = blockIdx.x, t = threadIdx.x, i = b * SB + t;

    int v = (i < NN) ? d_cnt[i] : 0;
    s[t] = v;
    __syncthreads();
    for (int o = 1; o < SB; o <<= 1) {
        int x = (t >= o) ? s[t - o] : 0;
        __syncthreads();
        s[t] += x;
        __syncthreads();
    }
    const int block_total = s[SB - 1];

    if (t == 0) {
        int prev = 0;
        if (b > 0) {
            int r;
            while ((r = atomicAdd(&d_incl[b - 1], 0)) == 0) { }
            prev = r - 1;
        }
        __threadfence();
        atomicExch(&d_incl[b], prev + block_total + 1);   // publish inclusive+1
        s_prev = prev;
    }
    __syncthreads();

    if (i < NN) {
        int o = s_prev + s[t] - v;       // global exclusive prefix
        d_off[i] = o;
        d_cnt[i] = o;                    // becomes scatter cursor
    }
    if (b == NBLK - 1 && t == 0) d_off[NN] = EE;
}

// 2 edges per thread: two independent atomic->store chains for ILP.
__global__ void k_scatter(const int2* __restrict__ src2, const int2* __restrict__ dst2) {
    int t = blockIdx.x * blockDim.x + threadIdx.x;
    if (t < EE / 2) {
        int2 d = __ldg(&dst2[t]);
        int2 s = __ldg(&src2[t]);
        int p0 = atomicAdd(&d_cnt[d.x], 1);
        int p1 = atomicAdd(&d_cnt[d.y], 1);
        d_csr_src[p0] = s.x;
        d_csr_src[p1] = s.y;
    }
}

// Tail reset: restore the zero-state invariant for the next replay.
// Runs concurrently with k_agg (agg does not touch d_cnt / d_incl).
__global__ void k_tail_zero() {
    int i = blockIdx.x * blockDim.x + threadIdx.x;
    if (i < NN) d_cnt[i] = 0;
    if (i < NBLK) d_incl[i] = 0;
}

// ---------------- GEMM via packed fma.rn.f32x2 ------------------------------
// z[n, h*16+d] = sum_k h[n,k] * Wfc[h*2048 + k*16 + d]
#define GBM 64

__device__ __forceinline__ ull fma2(ull a, ull b, ull c) {
    ull d;
    asm("fma.rn.f32x2 %0, %1, %2, %3;" : "=l"(d) : "l"(a), "l"(b), "l"(c));
    return d;
}
__device__ __forceinline__ ull pack2(float x) {
    ull d;
    asm("mov.b64 %0, {%1, %1};" : "=l"(d) : "f"(x));
    return d;
}

__global__ void __launch_bounds__(256) k_gemm(const float* __restrict__ hin,
                                              const float* __restrict__ Wfc) {
    extern __shared__ float smem[];
    float* sW = smem;                  // [128][128]  sW[k*128 + c]
    float* sH = smem + KK * CC;        // [64][128]   sH[node*128 + k]

    const int tid  = threadIdx.x;
    const int lane = tid & 31;
    const int warp = tid >> 5;
    const int base = blockIdx.x * GBM;
    const int n0   = warp * 8;

    {
        const float4* W4 = (const float4*)Wfc;
        float4* sW4 = (float4*)sW;
        for (int g = tid; g < KK * CC / 4; g += 256) {
            int k  = g >> 5;
            int hh = (g >> 2) & 7;
            int dq = g & 3;
            sW4[g] = W4[hh * 512 + k * 4 + dq];
        }
    }
    {
        const float4* H4 = (const float4*)hin;
        float4* sH4 = (float4*)sH;
        for (int g = tid; g < GBM * KK / 4; g += 256) {
            int row = g >> 5;
            int kq  = g & 31;
            int gn  = base + row;
            sH4[g] = (gn < NN) ? H4[gn * 32 + kq]
                               : make_float4(0.f, 0.f, 0.f, 0.f);
        }
    }
    __syncthreads();

    ull acc[8][2];
#pragma unroll
    for (int j = 0; j < 8; ++j) { acc[j][0] = 0ull; acc[j][1] = 0ull; }

    for (int k = 0; k < KK; k += 4) {
        ull w2[4][2];
#pragma unroll
        for (int kk = 0; kk < 4; ++kk) {
            ulonglong2 wv = *(const ulonglong2*)&sW[(k + kk) * CC + lane * 4];
            w2[kk][0] = wv.x;
            w2[kk][1] = wv.y;
        }
#pragma unroll
        for (int j = 0; j < 8; ++j) {
            const float4 hj = *(const float4*)&sH[(n0 + j) * KK + k];
            ull h0 = pack2(hj.x), h1 = pack2(hj.y), h2 = pack2(hj.z), h3 = pack2(hj.w);
            acc[j][0] = fma2(h0, w2[0][0], acc[j][0]);
            acc[j][1] = fma2(h0, w2[0][1], acc[j][1]);
            acc[j][0] = fma2(h1, w2[1][0], acc[j][0]);
            acc[j][1] = fma2(h1, w2[1][1], acc[j][1]);
            acc[j][0] = fma2(h2, w2[2][0], acc[j][0]);
            acc[j][1] = fma2(h2, w2[2][1], acc[j][1]);
            acc[j][0] = fma2(h3, w2[3][0], acc[j][0]);
            acc[j][1] = fma2(h3, w2[3][1], acc[j][1]);
        }
    }

#pragma unroll
    for (int j = 0; j < 8; ++j) {
        int gn = base + n0 + j;
        if (gn < NN) {
            float2 lo = *(float2*)&acc[j][0];
            float2 hi = *(float2*)&acc[j][1];
            *(float4*)&d_z[gn * CC + lane * 4] = make_float4(lo.x, lo.y, hi.x, hi.y);
        }
    }
}

// ---------------- per-dst-node softmax aggregation + epilogue ---------------
__device__ __forceinline__ float elu1(float v) {
    return v > 0.f ? v : expm1f(v);
}

__device__ __forceinline__ void edge_accum(const float4 za, const float4 zd,
                                           float& dx, float& dy, float& dz, float& dw,
                                           float& nx, float& ny, float& nz, float& nw) {
    float ex;
    ex = __expf(za.x * zd.x); dx += ex; nx += ex * za.x;
    ex = __expf(za.y * zd.y); dy += ex; ny += ex * za.y;
    ex = __expf(za.z * zd.z); dz += ex; nz += ex * za.z;
    ex = __expf(za.w * zd.w); dw += ex; nw += ex * za.w;
}

__global__ void __launch_bounds__(256) k_agg(const float* __restrict__ hin,
                                             const float* __restrict__ snorm,
                                             float* __restrict__ out) {
    const int gwarp = (blockIdx.x * blockDim.x + threadIdx.x) >> 5;
    const int lane  = threadIdx.x & 31;
    if (gwarp >= NN) return;
    const int node = gwarp;

    const float4 zd = *(const float4*)&d_z[node * CC + lane * 4];
    float dx = 0.f, dy = 0.f, dz = 0.f, dw = 0.f;
    float nx = 0.f, ny = 0.f, nz = 0.f, nw = 0.f;

    const int p0 = d_off[node];
    const int p1 = d_off[node + 1];

    int p = p0;
    for (; p + 3 < p1; p += 4) {
        int s0 = __ldg(&d_csr_src[p]);
        int s1 = __ldg(&d_csr_src[p + 1]);
        int s2 = __ldg(&d_csr_src[p + 2]);
        int s3 = __ldg(&d_csr_src[p + 3]);
        float4 z0 = *(const float4*)&d_z[s0 * CC + lane * 4];
        float4 z1 = *(const float4*)&d_z[s1 * CC + lane * 4];
        float4 z2 = *(const float4*)&d_z[s2 * CC + lane * 4];
        float4 z3 = *(const float4*)&d_z[s3 * CC + lane * 4];
        edge_accum(z0, zd, dx, dy, dz, dw, nx, ny, nz, nw);
        edge_accum(z1, zd, dx, dy, dz, dw, nx, ny, nz, nw);
        edge_accum(z2, zd, dx, dy, dz, dw, nx, ny, nz, nw);
        edge_accum(z3, zd, dx, dy, dz, dw, nx, ny, nz, nw);
    }
    for (; p < p1; ++p) {
        int s0 = __ldg(&d_csr_src[p]);
        float4 z0 = *(const float4*)&d_z[s0 * CC + lane * 4];
        edge_accum(z0, zd, dx, dy, dz, dw, nx, ny, nz, nw);
    }

    const float sn = __ldg(&snorm[node]);
    float4 hv = *(const float4*)&hin[node * CC + lane * 4];

    float rx = (dx > 0.f) ? __fdividef(1.f, dx) : 0.f;
    float ry = (dy > 0.f) ? __fdividef(1.f, dy) : 0.f;
    float rz = (dz > 0.f) ? __fdividef(1.f, dz) : 0.f;
    float rw = (dw > 0.f) ? __fdividef(1.f, dw) : 0.f;

    float4 o;
    o.x = hv.x + elu1(nx * rx * sn);
    o.y = hv.y + elu1(ny * ry * sn);
    o.z = hv.z + elu1(nz * rz * sn);
    o.w = hv.w + elu1(nw * rw * sn);

    *(float4*)&out[node * CC + lane * 4] = o;
}

// ---------------- launch ----------------------------------------------------
// Fork/join discipline for graph capture: EVERY operation enqueued on the side
// stream must be upstream of an event that the capture (default) stream waits
// on before kernel_launch returns. s2's chain: gemm -> evJoin -> (wait evScat)
// -> tail_zero -> evTail; stream 0 waits evJoin (before agg) and evTail (after
// agg), so the branch is fully joined at capture end.
extern "C" void kernel_launch(void* const* d_in, const int* in_sizes, int n_in,
                              void* d_out, int out_size) {
    const float* hin   = (const float*)d_in[0];   // [N,128]
    const float* snorm = (const float*)d_in[1];   // [N,1]
    const float* Wfc   = (const float*)d_in[2];   // [8,128,16]
    const int*   src   = (const int*)d_in[3];     // [E]
    const int*   dst   = (const int*)d_in[4];     // [E]
    float* out = (float*)d_out;                   // [N,128]

    const int gemm_smem = (KK * CC + GBM * KK) * sizeof(float);   // 96 KB

    static int init_done = 0;
    static cudaStream_t s2 = 0;
    static cudaEvent_t evFork = 0, evJoin = 0, evScat = 0, evTail = 0;
    if (!init_done) {
        cudaFuncSetAttribute(k_gemm, cudaFuncAttributeMaxDynamicSharedMemorySize,
                             gemm_smem);
        if (cudaStreamCreateWithFlags(&s2, cudaStreamNonBlocking) != cudaSuccess)
            s2 = 0;
        if (s2) {
            if (cudaEventCreateWithFlags(&evFork, cudaEventDisableTiming) != cudaSuccess ||
                cudaEventCreateWithFlags(&evJoin, cudaEventDisableTiming) != cudaSuccess ||
                cudaEventCreateWithFlags(&evScat, cudaEventDisableTiming) != cudaSuccess ||
                cudaEventCreateWithFlags(&evTail, cudaEventDisableTiming) != cudaSuccess) {
                s2 = 0;   // deterministic serial fallback
            }
        }
        init_done = 1;
    }

    if (s2) {
        // Fork GEMM onto s2 (depends only on hin/Wfc).
        cudaEventRecord(evFork, 0);
        cudaStreamWaitEvent(s2, evFork, 0);
        k_gemm<<<(NN + GBM - 1) / GBM, 256, gemm_smem, s2>>>(hin, Wfc);
        cudaEventRecord(evJoin, s2);
    }

    // CSR chain on the default stream. d_cnt/d_incl are zero on entry
    // (module load on call 1, tail-zero of the previous call thereafter;
    // graph replays fully serialize on the harness stream).
    k_hist<<<(EE / 4 + 255) / 256, 256>>>((const int4*)dst);
    k_scan<<<NBLK, SB>>>();
    k_scatter<<<(EE / 2 + 255) / 256, 256>>>((const int2*)src, (const int2*)dst);

    if (s2) {
        cudaEventRecord(evScat, 0);
        cudaStreamWaitEvent(s2, evScat, 0);            // after last d_cnt use
        k_tail_zero<<<(NN + 255) / 256, 256, 0, s2>>>(); // overlaps agg
        cudaEventRecord(evTail, s2);                   // rejoin marker
        cudaStreamWaitEvent(0, evJoin, 0);             // agg needs d_z
        k_agg<<<(NN * 32 + 255) / 256, 256>>>(hin, snorm, out);
        cudaStreamWaitEvent(0, evTail, 0);             // fully join s2 branch
    } else {
        k_gemm<<<(NN + GBM - 1) / GBM, 256, gemm_smem>>>(hin, Wfc);
        k_agg<<<(NN * 32 + 255) / 256, 256>>>(hin, snorm, out);
        k_tail_zero<<<(NN + 255) / 256, 256>>>();
    }
}

// round 9
// speedup vs baseline: 1.5215x; 1.5215x over previous
#include <cuda_runtime.h>
#include <cuda_bf16.h>
#include <cstdint>

// Problem constants:
//   N=50000 nodes, E=800000 edges, IN_DIM=128, H=8, D=16 -> C = H*D = 128
#define NN 50000
#define EE 800000
#define CC 128
#define KK 128

typedef unsigned long long ull;

// ---------------- device scratch --------------------------------------------
__device__ float d_z[NN * CC];          // per-node projected features [N,128]
__device__ int   d_cnt[NN];             // degree histogram -> scatter cursor
__device__ int   d_off[NN + 1];         // CSR row offsets by dst
__device__ int   d_csr_src[EE];         // src ids grouped by dst

#define SB   512
#define NBLK ((NN + SB - 1) / SB)       // 98
__device__ int d_btot[NBLK];            // per-block totals from scan1

// ---------------- CSR construction ------------------------------------------
__global__ void k_zero_cnt() {
    int i = blockIdx.x * blockDim.x + threadIdx.x;
    if (i < NN) d_cnt[i] = 0;
}

// 4 edges per thread via one int4 load (E divisible by 4).
__global__ void k_hist(const int4* __restrict__ dst4) {
    int t = blockIdx.x * blockDim.x + threadIdx.x;
    if (t < EE / 4) {
        int4 d = __ldg(&dst4[t]);
        atomicAdd(&d_cnt[d.x], 1);
        atomicAdd(&d_cnt[d.y], 1);
        atomicAdd(&d_cnt[d.z], 1);
        atomicAdd(&d_cnt[d.w], 1);
    }
}

// Stage 1: per-block exclusive scan; publish block totals.
__global__ void __launch_bounds__(SB) k_scan1() {
    __shared__ int s[SB];
    const int b = blockIdx.x, t = threadIdx.x, i = b * SB + t;
    int v = (i < NN) ? d_cnt[i] : 0;
    s[t] = v;
    __syncthreads();
    for (int o = 1; o < SB; o <<= 1) {
        int x = (t >= o) ? s[t - o] : 0;
        __syncthreads();
        s[t] += x;
        __syncthreads();
    }
    if (i < NN) d_off[i] = s[t] - v;          // exclusive within block
    if (t == SB - 1) d_btot[b] = s[t];
}

// Stage 2 (merged scan2+scan3): every block redundantly scans the 98 block
// totals in shared memory (no inter-block dependency), then applies its own
// block offset. Also initializes the scatter cursor.
__global__ void __launch_bounds__(SB) k_scan3() {
    __shared__ int sb[128];
    const int b = blockIdx.x, t = threadIdx.x, i = b * SB + t;

    if (t < 128) sb[t] = (t < NBLK) ? d_btot[t] : 0;
    __syncthreads();
    // Hillis-Steele inclusive scan over 128 slots, done by threads 0..127
    for (int o = 1; o < 128; o <<= 1) {
        int x = (t < 128 && t >= o) ? sb[t - o] : 0;
        __syncthreads();
        if (t < 128) sb[t] += x;
        __syncthreads();
    }
    const int boff = (b > 0) ? sb[b - 1] : 0;  // exclusive prefix of this block

    if (i < NN) {
        int o = d_off[i] + boff;
        d_off[i] = o;
        d_cnt[i] = o;                          // becomes scatter cursor
    }
    if (b == NBLK - 1 && t == 0) d_off[NN] = EE;
}

__global__ void k_scatter(const int* __restrict__ src, const int* __restrict__ dst) {
    int e = blockIdx.x * blockDim.x + threadIdx.x;
    if (e < EE) {
        int pos = atomicAdd(&d_cnt[dst[e]], 1);
        d_csr_src[pos] = src[e];
    }
}

// ---------------- GEMM via packed fma.rn.f32x2 ------------------------------
// z[n, h*16+d] = sum_k h[n,k] * Wfc[h*2048 + k*16 + d]
#define GBM 64

__device__ __forceinline__ ull fma2(ull a, ull b, ull c) {
    ull d;
    asm("fma.rn.f32x2 %0, %1, %2, %3;" : "=l"(d) : "l"(a), "l"(b), "l"(c));
    return d;
}
__device__ __forceinline__ ull pack2(float x) {
    ull d;
    asm("mov.b64 %0, {%1, %1};" : "=l"(d) : "f"(x));
    return d;
}

__global__ void __launch_bounds__(256) k_gemm(const float* __restrict__ hin,
                                              const float* __restrict__ Wfc) {
    extern __shared__ float smem[];
    float* sW = smem;                  // [128][128]  sW[k*128 + c]
    float* sH = smem + KK * CC;        // [64][128]   sH[node*128 + k]

    const int tid  = threadIdx.x;
    const int lane = tid & 31;
    const int warp = tid >> 5;
    const int base = blockIdx.x * GBM;
    const int n0   = warp * 8;

    {
        const float4* W4 = (const float4*)Wfc;
        float4* sW4 = (float4*)sW;
        for (int g = tid; g < KK * CC / 4; g += 256) {
            int k  = g >> 5;
            int hh = (g >> 2) & 7;
            int dq = g & 3;
            sW4[g] = W4[hh * 512 + k * 4 + dq];
        }
    }
    {
        const float4* H4 = (const float4*)hin;
        float4* sH4 = (float4*)sH;
        for (int g = tid; g < GBM * KK / 4; g += 256) {
            int row = g >> 5;
            int kq  = g & 31;
            int gn  = base + row;
            sH4[g] = (gn < NN) ? H4[gn * 32 + kq]
                               : make_float4(0.f, 0.f, 0.f, 0.f);
        }
    }
    __syncthreads();

    ull acc[8][2];
#pragma unroll
    for (int j = 0; j < 8; ++j) { acc[j][0] = 0ull; acc[j][1] = 0ull; }

    for (int k = 0; k < KK; k += 4) {
        ull w2[4][2];
#pragma unroll
        for (int kk = 0; kk < 4; ++kk) {
            ulonglong2 wv = *(const ulonglong2*)&sW[(k + kk) * CC + lane * 4];
            w2[kk][0] = wv.x;
            w2[kk][1] = wv.y;
        }
#pragma unroll
        for (int j = 0; j < 8; ++j) {
            const float4 hj = *(const float4*)&sH[(n0 + j) * KK + k];
            ull h0 = pack2(hj.x), h1 = pack2(hj.y), h2 = pack2(hj.z), h3 = pack2(hj.w);
            acc[j][0] = fma2(h0, w2[0][0], acc[j][0]);
            acc[j][1] = fma2(h0, w2[0][1], acc[j][1]);
            acc[j][0] = fma2(h1, w2[1][0], acc[j][0]);
            acc[j][1] = fma2(h1, w2[1][1], acc[j][1]);
            acc[j][0] = fma2(h2, w2[2][0], acc[j][0]);
            acc[j][1] = fma2(h2, w2[2][1], acc[j][1]);
            acc[j][0] = fma2(h3, w2[3][0], acc[j][0]);
            acc[j][1] = fma2(h3, w2[3][1], acc[j][1]);
        }
    }

#pragma unroll
    for (int j = 0; j < 8; ++j) {
        int gn = base + n0 + j;
        if (gn < NN) {
            float2 lo = *(float2*)&acc[j][0];
            float2 hi = *(float2*)&acc[j][1];
            *(float4*)&d_z[gn * CC + lane * 4] = make_float4(lo.x, lo.y, hi.x, hi.y);
        }
    }
}

// ---------------- per-dst-node softmax aggregation + epilogue ---------------
__device__ __forceinline__ float elu1(float v) {
    return v > 0.f ? v : expm1f(v);
}

__device__ __forceinline__ void edge_accum(const float4 za, const float4 zd,
                                           float& dx, float& dy, float& dz, float& dw,
                                           float& nx, float& ny, float& nz, float& nw) {
    float ex;
    ex = __expf(za.x * zd.x); dx += ex; nx += ex * za.x;
    ex = __expf(za.y * zd.y); dy += ex; ny += ex * za.y;
    ex = __expf(za.z * zd.z); dz += ex; nz += ex * za.z;
    ex = __expf(za.w * zd.w); dw += ex; nw += ex * za.w;
}

__global__ void __launch_bounds__(256) k_agg(const float* __restrict__ hin,
                                             const float* __restrict__ snorm,
                                             float* __restrict__ out) {
    const int gwarp = (blockIdx.x * blockDim.x + threadIdx.x) >> 5;
    const int lane  = threadIdx.x & 31;
    if (gwarp >= NN) return;
    const int node = gwarp;

    const float4 zd = *(const float4*)&d_z[node * CC + lane * 4];
    float dx = 0.f, dy = 0.f, dz = 0.f, dw = 0.f;
    float nx = 0.f, ny = 0.f, nz = 0.f, nw = 0.f;

    const int p0 = d_off[node];
    const int p1 = d_off[node + 1];

    int p = p0;
    for (; p + 3 < p1; p += 4) {
        int s0 = __ldg(&d_csr_src[p]);
        int s1 = __ldg(&d_csr_src[p + 1]);
        int s2 = __ldg(&d_csr_src[p + 2]);
        int s3 = __ldg(&d_csr_src[p + 3]);
        float4 z0 = *(const float4*)&d_z[s0 * CC + lane * 4];
        float4 z1 = *(const float4*)&d_z[s1 * CC + lane * 4];
        float4 z2 = *(const float4*)&d_z[s2 * CC + lane * 4];
        float4 z3 = *(const float4*)&d_z[s3 * CC + lane * 4];
        edge_accum(z0, zd, dx, dy, dz, dw, nx, ny, nz, nw);
        edge_accum(z1, zd, dx, dy, dz, dw, nx, ny, nz, nw);
        edge_accum(z2, zd, dx, dy, dz, dw, nx, ny, nz, nw);
        edge_accum(z3, zd, dx, dy, dz, dw, nx, ny, nz, nw);
    }
    for (; p < p1; ++p) {
        int s0 = __ldg(&d_csr_src[p]);
        float4 z0 = *(const float4*)&d_z[s0 * CC + lane * 4];
        edge_accum(z0, zd, dx, dy, dz, dw, nx, ny, nz, nw);
    }

    const float sn = __ldg(&snorm[node]);
    float4 hv = *(const float4*)&hin[node * CC + lane * 4];

    float rx = (dx > 0.f) ? __fdividef(1.f, dx) : 0.f;
    float ry = (dy > 0.f) ? __fdividef(1.f, dy) : 0.f;
    float rz = (dz > 0.f) ? __fdividef(1.f, dz) : 0.f;
    float rw = (dw > 0.f) ? __fdividef(1.f, dw) : 0.f;

    float4 o;
    o.x = hv.x + elu1(nx * rx * sn);
    o.y = hv.y + elu1(ny * ry * sn);
    o.z = hv.z + elu1(nz * rz * sn);
    o.w = hv.w + elu1(nw * rw * sn);

    *(float4*)&out[node * CC + lane * 4] = o;
}

// ---------------- launch ----------------------------------------------------
// R5-proven topology: CSR chain on stream 0; GEMM forked onto s2; s2's last op
// is the evJoin record, which stream 0 consumes before k_agg (branch joined).
extern "C" void kernel_launch(void* const* d_in, const int* in_sizes, int n_in,
                              void* d_out, int out_size) {
    const float* hin   = (const float*)d_in[0];   // [N,128]
    const float* snorm = (const float*)d_in[1];   // [N,1]
    const float* Wfc   = (const float*)d_in[2];   // [8,128,16]
    const int*   src   = (const int*)d_in[3];     // [E]
    const int*   dst   = (const int*)d_in[4];     // [E]
    float* out = (float*)d_out;                   // [N,128]

    const int gemm_smem = (KK * CC + GBM * KK) * sizeof(float);   // 96 KB

    static int init_done = 0;
    static cudaStream_t s2 = 0;
    static cudaEvent_t evFork = 0, evJoin = 0;
    if (!init_done) {
        cudaFuncSetAttribute(k_gemm, cudaFuncAttributeMaxDynamicSharedMemorySize,
                             gemm_smem);
        if (cudaStreamCreateWithFlags(&s2, cudaStreamNonBlocking) != cudaSuccess)
            s2 = 0;
        if (s2) {
            if (cudaEventCreateWithFlags(&evFork, cudaEventDisableTiming) != cudaSuccess ||
                cudaEventCreateWithFlags(&evJoin, cudaEventDisableTiming) != cudaSuccess) {
                s2 = 0;   // deterministic serial fallback
            }
        }
        init_done = 1;
    }

    if (s2) {
        cudaEventRecord(evFork, 0);
        cudaStreamWaitEvent(s2, evFork, 0);
        k_gemm<<<(NN + GBM - 1) / GBM, 256, gemm_smem, s2>>>(hin, Wfc);
        cudaEventRecord(evJoin, s2);
    }

    // CSR chain on the default stream.
    k_zero_cnt<<<(NN + 255) / 256, 256>>>();
    k_hist<<<(EE / 4 + 255) / 256, 256>>>((const int4*)dst);
    k_scan1<<<NBLK, SB>>>();
    k_scan3<<<NBLK, SB>>>();
    k_scatter<<<(EE + 255) / 256, 256>>>(src, dst);

    if (s2) {
        cudaStreamWaitEvent(0, evJoin, 0);    // join: agg needs d_z + CSR
    } else {
        k_gemm<<<(NN + GBM - 1) / GBM, 256, gemm_smem>>>(hin, Wfc);
    }

    k_agg<<<(NN * 32 + 255) / 256, 256>>>(hin, snorm, out);
}

// round 10
// speedup vs baseline: 1.5919x; 1.0463x over previous
#include <cuda_runtime.h>
#include <cuda_bf16.h>
#include <cstdint>

// Problem constants:
//   N=50000 nodes, E=800000 edges, IN_DIM=128, H=8, D=16 -> C = H*D = 128
#define NN 50000
#define EE 800000
#define CC 128
#define KK 128

typedef unsigned long long ull;

// ---------------- device scratch (zero-initialized at module load) ----------
__device__ float d_z[NN * CC];          // per-node projected features [N,128]
__device__ int   d_cnt[NN];             // degree hist -> scatter cursor (tail-zeroed)
__device__ int   d_off[NN + 1];         // CSR row offsets by dst
__device__ int   d_csr_src[EE];         // src ids grouped by dst

#define SB   512
#define NBLK ((NN + SB - 1) / SB)       // 98
__device__ int d_btot[NBLK];            // per-block totals from scan1

// ---------------- CSR construction ------------------------------------------
// 4 edges per thread via one int4 load (E divisible by 4).
// Requires d_cnt == 0 on entry (module load on call 1; tail-zero thereafter).
__global__ void k_hist(const int4* __restrict__ dst4) {
    int t = blockIdx.x * blockDim.x + threadIdx.x;
    if (t < EE / 4) {
        int4 d = __ldg(&dst4[t]);
        atomicAdd(&d_cnt[d.x], 1);
        atomicAdd(&d_cnt[d.y], 1);
        atomicAdd(&d_cnt[d.z], 1);
        atomicAdd(&d_cnt[d.w], 1);
    }
}

// Stage 1: per-block exclusive scan; publish block totals.
__global__ void __launch_bounds__(SB) k_scan1() {
    __shared__ int s[SB];
    const int b = blockIdx.x, t = threadIdx.x, i = b * SB + t;
    int v = (i < NN) ? d_cnt[i] : 0;
    s[t] = v;
    __syncthreads();
    for (int o = 1; o < SB; o <<= 1) {
        int x = (t >= o) ? s[t - o] : 0;
        __syncthreads();
        s[t] += x;
        __syncthreads();
    }
    if (i < NN) d_off[i] = s[t] - v;          // exclusive within block
    if (t == SB - 1) d_btot[b] = s[t];
}

// Stage 2: every block redundantly scans the 98 block totals (no inter-block
// dependency, no spin), then applies its own block offset + inits cursor.
__global__ void __launch_bounds__(SB) k_scan3() {
    __shared__ int sb[128];
    const int b = blockIdx.x, t = threadIdx.x, i = b * SB + t;

    if (t < 128) sb[t] = (t < NBLK) ? d_btot[t] : 0;
    __syncthreads();
    for (int o = 1; o < 128; o <<= 1) {
        int x = (t < 128 && t >= o) ? sb[t - o] : 0;
        __syncthreads();
        if (t < 128) sb[t] += x;
        __syncthreads();
    }
    const int boff = (b > 0) ? sb[b - 1] : 0;

    if (i < NN) {
        int o = d_off[i] + boff;
        d_off[i] = o;
        d_cnt[i] = o;                          // becomes scatter cursor
    }
    if (b == NBLK - 1 && t == 0) d_off[NN] = EE;
}

__global__ void k_scatter(const int* __restrict__ src, const int* __restrict__ dst) {
    int e = blockIdx.x * blockDim.x + threadIdx.x;
    if (e < EE) {
        int pos = atomicAdd(&d_cnt[dst[e]], 1);
        d_csr_src[pos] = src[e];
    }
}

// Tail reset: restore d_cnt == 0 for the next replay. Runs on s2 concurrently
// with k_agg (agg never touches d_cnt).
__global__ void k_tail_zero() {
    int i = blockIdx.x * blockDim.x + threadIdx.x;
    if (i < NN) d_cnt[i] = 0;
}

// ---------------- GEMM via packed fma.rn.f32x2 ------------------------------
// z[n, h*16+d] = sum_k h[n,k] * Wfc[h*2048 + k*16 + d]
#define GBM 64

__device__ __forceinline__ ull fma2(ull a, ull b, ull c) {
    ull d;
    asm("fma.rn.f32x2 %0, %1, %2, %3;" : "=l"(d) : "l"(a), "l"(b), "l"(c));
    return d;
}
__device__ __forceinline__ ull pack2(float x) {
    ull d;
    asm("mov.b64 %0, {%1, %1};" : "=l"(d) : "f"(x));
    return d;
}

__global__ void __launch_bounds__(256) k_gemm(const float* __restrict__ hin,
                                              const float* __restrict__ Wfc) {
    extern __shared__ float smem[];
    float* sW = smem;                  // [128][128]  sW[k*128 + c]
    float* sH = smem + KK * CC;        // [64][128]   sH[node*128 + k]

    const int tid  = threadIdx.x;
    const int lane = tid & 31;
    const int warp = tid >> 5;
    const int base = blockIdx.x * GBM;
    const int n0   = warp * 8;

    {
        const float4* W4 = (const float4*)Wfc;
        float4* sW4 = (float4*)sW;
        for (int g = tid; g < KK * CC / 4; g += 256) {
            int k  = g >> 5;
            int hh = (g >> 2) & 7;
            int dq = g & 3;
            sW4[g] = W4[hh * 512 + k * 4 + dq];
        }
    }
    {
        const float4* H4 = (const float4*)hin;
        float4* sH4 = (float4*)sH;
        for (int g = tid; g < GBM * KK / 4; g += 256) {
            int row = g >> 5;
            int kq  = g & 31;
            int gn  = base + row;
            sH4[g] = (gn < NN) ? H4[gn * 32 + kq]
                               : make_float4(0.f, 0.f, 0.f, 0.f);
        }
    }
    __syncthreads();

    ull acc[8][2];
#pragma unroll
    for (int j = 0; j < 8; ++j) { acc[j][0] = 0ull; acc[j][1] = 0ull; }

    for (int k = 0; k < KK; k += 4) {
        ull w2[4][2];
#pragma unroll
        for (int kk = 0; kk < 4; ++kk) {
            ulonglong2 wv = *(const ulonglong2*)&sW[(k + kk) * CC + lane * 4];
            w2[kk][0] = wv.x;
            w2[kk][1] = wv.y;
        }
#pragma unroll
        for (int j = 0; j < 8; ++j) {
            const float4 hj = *(const float4*)&sH[(n0 + j) * KK + k];
            ull h0 = pack2(hj.x), h1 = pack2(hj.y), h2 = pack2(hj.z), h3 = pack2(hj.w);
            acc[j][0] = fma2(h0, w2[0][0], acc[j][0]);
            acc[j][1] = fma2(h0, w2[0][1], acc[j][1]);
            acc[j][0] = fma2(h1, w2[1][0], acc[j][0]);
            acc[j][1] = fma2(h1, w2[1][1], acc[j][1]);
            acc[j][0] = fma2(h2, w2[2][0], acc[j][0]);
            acc[j][1] = fma2(h2, w2[2][1], acc[j][1]);
            acc[j][0] = fma2(h3, w2[3][0], acc[j][0]);
            acc[j][1] = fma2(h3, w2[3][1], acc[j][1]);
        }
    }

#pragma unroll
    for (int j = 0; j < 8; ++j) {
        int gn = base + n0 + j;
        if (gn < NN) {
            float2 lo = *(float2*)&acc[j][0];
            float2 hi = *(float2*)&acc[j][1];
            *(float4*)&d_z[gn * CC + lane * 4] = make_float4(lo.x, lo.y, hi.x, hi.y);
        }
    }
}

// ---------------- per-dst-node softmax aggregation + epilogue ---------------
// exp(za*zd) computed as exp2(za*(zd*log2e)): log2e folded into the node-
// resident zd once per warp, saving one FMUL per exp in the edge loop.
// __expf(x) = exp2(x*log2e) internally, so this is the same approximation
// with a different rounding association (error ~1e-7, threshold 1e-3).
__device__ __forceinline__ float elu1(float v) {
    return v > 0.f ? v : expm1f(v);
}

__device__ __forceinline__ void edge_accum(const float4 za, const float4 zds,
                                           float& dx, float& dy, float& dz, float& dw,
                                           float& nx, float& ny, float& nz, float& nw) {
    float ex;
    ex = exp2f(za.x * zds.x); dx += ex; nx += ex * za.x;
    ex = exp2f(za.y * zds.y); dy += ex; ny += ex * za.y;
    ex = exp2f(za.z * zds.z); dz += ex; nz += ex * za.z;
    ex = exp2f(za.w * zds.w); dw += ex; nw += ex * za.w;
}

__global__ void __launch_bounds__(256) k_agg(const float* __restrict__ hin,
                                             const float* __restrict__ snorm,
                                             float* __restrict__ out) {
    const int gwarp = (blockIdx.x * blockDim.x + threadIdx.x) >> 5;
    const int lane  = threadIdx.x & 31;
    if (gwarp >= NN) return;
    const int node = gwarp;

    const float LOG2E = 1.4426950408889634f;
    float4 zds = *(const float4*)&d_z[node * CC + lane * 4];
    zds.x *= LOG2E; zds.y *= LOG2E; zds.z *= LOG2E; zds.w *= LOG2E;

    float dx = 0.f, dy = 0.f, dz = 0.f, dw = 0.f;
    float nx = 0.f, ny = 0.f, nz = 0.f, nw = 0.f;

    const int p0 = d_off[node];
    const int p1 = d_off[node + 1];

    int p = p0;
    for (; p + 3 < p1; p += 4) {
        int s0 = __ldg(&d_csr_src[p]);
        int s1 = __ldg(&d_csr_src[p + 1]);
        int s2 = __ldg(&d_csr_src[p + 2]);
        int s3 = __ldg(&d_csr_src[p + 3]);
        float4 z0 = *(const float4*)&d_z[s0 * CC + lane * 4];
        float4 z1 = *(const float4*)&d_z[s1 * CC + lane * 4];
        float4 z2 = *(const float4*)&d_z[s2 * CC + lane * 4];
        float4 z3 = *(const float4*)&d_z[s3 * CC + lane * 4];
        edge_accum(z0, zds, dx, dy, dz, dw, nx, ny, nz, nw);
        edge_accum(z1, zds, dx, dy, dz, dw, nx, ny, nz, nw);
        edge_accum(z2, zds, dx, dy, dz, dw, nx, ny, nz, nw);
        edge_accum(z3, zds, dx, dy, dz, dw, nx, ny, nz, nw);
    }
    for (; p < p1; ++p) {
        int s0 = __ldg(&d_csr_src[p]);
        float4 z0 = *(const float4*)&d_z[s0 * CC + lane * 4];
        edge_accum(z0, zds, dx, dy, dz, dw, nx, ny, nz, nw);
    }

    const float sn = __ldg(&snorm[node]);
    float4 hv = *(const float4*)&hin[node * CC + lane * 4];

    float rx = (dx > 0.f) ? __fdividef(1.f, dx) : 0.f;
    float ry = (dy > 0.f) ? __fdividef(1.f, dy) : 0.f;
    float rz = (dz > 0.f) ? __fdividef(1.f, dz) : 0.f;
    float rw = (dw > 0.f) ? __fdividef(1.f, dw) : 0.f;

    float4 o;
    o.x = hv.x + elu1(nx * rx * sn);
    o.y = hv.y + elu1(ny * ry * sn);
    o.z = hv.z + elu1(nz * rz * sn);
    o.w = hv.w + elu1(nw * rw * sn);

    *(float4*)&out[node * CC + lane * 4] = o;
}

// ---------------- launch ----------------------------------------------------
// Fork/join for capture: s2's chain is gemm -> evJoin -> (wait evScat) ->
// tail_zero -> evTail. Stream 0 waits evJoin before agg and evTail after agg,
// so the side branch is fully joined when kernel_launch returns.
extern "C" void kernel_launch(void* const* d_in, const int* in_sizes, int n_in,
                              void* d_out, int out_size) {
    const float* hin   = (const float*)d_in[0];   // [N,128]
    const float* snorm = (const float*)d_in[1];   // [N,1]
    const float* Wfc   = (const float*)d_in[2];   // [8,128,16]
    const int*   src   = (const int*)d_in[3];     // [E]
    const int*   dst   = (const int*)d_in[4];     // [E]
    float* out = (float*)d_out;                   // [N,128]

    const int gemm_smem = (KK * CC + GBM * KK) * sizeof(float);   // 96 KB

    static int init_done = 0;
    static cudaStream_t s2 = 0;
    static cudaEvent_t evFork = 0, evJoin = 0, evScat = 0, evTail = 0;
    if (!init_done) {
        cudaFuncSetAttribute(k_gemm, cudaFuncAttributeMaxDynamicSharedMemorySize,
                             gemm_smem);
        if (cudaStreamCreateWithFlags(&s2, cudaStreamNonBlocking) != cudaSuccess)
            s2 = 0;
        if (s2) {
            if (cudaEventCreateWithFlags(&evFork, cudaEventDisableTiming) != cudaSuccess ||
                cudaEventCreateWithFlags(&evJoin, cudaEventDisableTiming) != cudaSuccess ||
                cudaEventCreateWithFlags(&evScat, cudaEventDisableTiming) != cudaSuccess ||
                cudaEventCreateWithFlags(&evTail, cudaEventDisableTiming) != cudaSuccess) {
                s2 = 0;   // deterministic serial fallback
            }
        }
        init_done = 1;
    }

    if (s2) {
        cudaEventRecord(evFork, 0);
        cudaStreamWaitEvent(s2, evFork, 0);
        k_gemm<<<(NN + GBM - 1) / GBM, 256, gemm_smem, s2>>>(hin, Wfc);
        cudaEventRecord(evJoin, s2);
    }

    // CSR chain on the default stream (d_cnt == 0 invariant on entry).
    k_hist<<<(EE / 4 + 255) / 256, 256>>>((const int4*)dst);
    k_scan1<<<NBLK, SB>>>();
    k_scan3<<<NBLK, SB>>>();
    k_scatter<<<(EE + 255) / 256, 256>>>(src, dst);

    if (s2) {
        cudaEventRecord(evScat, 0);
        cudaStreamWaitEvent(s2, evScat, 0);              // after last d_cnt use
        k_tail_zero<<<(NN + 255) / 256, 256, 0, s2>>>(); // overlaps agg
        cudaEventRecord(evTail, s2);
        cudaStreamWaitEvent(0, evJoin, 0);               // agg needs d_z
        k_agg<<<(NN * 32 + 255) / 256, 256>>>(hin, snorm, out);
        cudaStreamWaitEvent(0, evTail, 0);               // fully join s2
    } else {
        k_gemm<<<(NN + GBM - 1) / GBM, 256, gemm_smem>>>(hin, Wfc);
        k_agg<<<(NN * 32 + 255) / 256, 256>>>(hin, snorm, out);
        k_tail_zero<<<(NN + 255) / 256, 256>>>();
    }
}